// round 5
// baseline (speedup 1.0000x reference)
#include <cuda_runtime.h>
#include <math.h>

// ---------------- scratch (device globals; no allocation allowed) ----------
// offsets (floats)
#define OFF_LIG     0           // 512*128
#define OFF_POC     65536       // 1024*128
#define OFF_M       196608      // 512*1024
#define OFF_SWL     720896      // 512*1024
#define OFF_SWP     1245184     // 1024*512
#define OFF_AGGL    1769472     // 512*128
#define OFF_AGGP    1835008     // 1024*128
#define OFF_LIGE    1966080     // 512*128
#define OFF_POCE    2031616     // 1024*128
#define OFF_QKVL    2162688     // 512*384
#define OFF_QKVP    2359296     // 1024*384
#define OFF_SL      2752512     // 8*512*1024
#define OFF_SP      6946816     // 8*1024*512
#define OFF_ATTL    11141120    // 512*128
#define OFF_ATTP    11206656    // 1024*128
#define OFF_APL     11337728    // 512*128
#define OFF_APP     11403264    // 1024*128
#define OFF_WM      11534336    // 64
#define OFF_MC      11534400    // 1
#define SCRATCH_FLOATS 11534464

__device__ float g_scratch[SCRATCH_FLOATS];

// ---------------- f32x2 packed helpers -------------------------------------
__device__ __forceinline__ unsigned long long pack2(float x, float y) {
    unsigned long long r;
    asm("mov.b64 %0, {%1, %2};" : "=l"(r) : "f"(x), "f"(y));
    return r;
}
__device__ __forceinline__ void unpack2(unsigned long long v, float& x, float& y) {
    asm("mov.b64 {%0, %1}, %2;" : "=f"(x), "=f"(y) : "l"(v));
}
__device__ __forceinline__ unsigned long long fma2(unsigned long long a,
                                                   unsigned long long b,
                                                   unsigned long long c) {
    unsigned long long d;
    asm("fma.rn.f32x2 %0, %1, %2, %3;" : "=l"(d) : "l"(a), "l"(b), "l"(c));
    return d;
}

// ---------------- block reductions ------------------------------------------
__device__ __forceinline__ float blkSum(float v) {
    __shared__ float sm[8];
    #pragma unroll
    for (int o = 16; o > 0; o >>= 1) v += __shfl_xor_sync(0xffffffffu, v, o);
    unsigned nw = blockDim.x >> 5;
    if ((threadIdx.x & 31) == 0) sm[threadIdx.x >> 5] = v;
    __syncthreads();
    float r = 0.f;
    for (unsigned w = 0; w < nw; w++) r += sm[w];
    __syncthreads();
    return r;
}
__device__ __forceinline__ float blkMax(float v) {
    __shared__ float sm2[8];
    #pragma unroll
    for (int o = 16; o > 0; o >>= 1) v = fmaxf(v, __shfl_xor_sync(0xffffffffu, v, o));
    unsigned nw = blockDim.x >> 5;
    if ((threadIdx.x & 31) == 0) sm2[threadIdx.x >> 5] = v;
    __syncthreads();
    float r = -3.4e38f;
    for (unsigned w = 0; w < nw; w++) r = fmaxf(r, sm2[w]);
    __syncthreads();
    return r;
}

// ---------------- prep: column-means of Wd3, mean of bd3 --------------------
__global__ void k_prep(const float* __restrict__ Wd3, const float* __restrict__ bd3,
                       float* __restrict__ wm, float* __restrict__ mc) {
    int t = threadIdx.x;
    if (t < 64) {
        float s = 0.f;
        for (int i = 0; i < 128; i++) s += Wd3[i * 64 + t];
        wm[t] = s * (1.f / 128.f);
    }
    if (t == 0) {
        float s = 0.f;
        for (int i = 0; i < 128; i++) s += bd3[i];
        *mc = s * (1.f / 128.f);
    }
}

// ---------------- Y[M,N] = X[M,K] @ W[N,K]^T + b, 16 rows/block --------------
// grid(M/16, ceil(N/128)), block 128. K <= 128, multiple of 4.
__global__ void __launch_bounds__(128) k_linear(const float* __restrict__ X,
                                                const float* __restrict__ W,
                                                const float* __restrict__ bias,
                                                float* __restrict__ Y,
                                                int K, int N) {
    __shared__ __align__(16) float Xs[16 * 128];
    int tid = threadIdx.x;
    int r0 = blockIdx.x * 16;
    int c = blockIdx.y * 128 + tid;
    int nf4 = 4 * K;  // number of float4 for 16 rows
    const float4* xsrc = (const float4*)(X + (size_t)r0 * K);
    float4* xdst = (float4*)Xs;
    for (int idx = tid; idx < nf4; idx += 128) xdst[idx] = xsrc[idx];
    __syncthreads();
    float acc[16];
    float bv = bias[c];
    #pragma unroll
    for (int r = 0; r < 16; r++) acc[r] = bv;
    const float* w = W + (size_t)c * K;
    #pragma unroll 4
    for (int k = 0; k < K; k++) {
        float wv = w[k];
        #pragma unroll
        for (int r = 0; r < 16; r++) acc[r] = fmaf(Xs[r * K + k], wv, acc[r]);
    }
    #pragma unroll
    for (int r = 0; r < 16; r++) Y[(size_t)(r0 + r) * N + c] = acc[r];
}

// ---------------- pair kernel: m[i][j] ---------------------------------------
// grid(512, 2), block 256. Each thread does 2 pocket indices, packed f32x2.
__global__ void __launch_bounds__(256) k_pair(const float* __restrict__ lc,
                                              const float* __restrict__ pc,
                                              const float* __restrict__ Wd1,
                                              const float* __restrict__ bd1,
                                              const float* __restrict__ Wd2,
                                              const float* __restrict__ bd2,
                                              const float* __restrict__ wm,
                                              const float* __restrict__ mc,
                                              float* __restrict__ M) {
    __shared__ __align__(16) unsigned long long wd2s[64 * 32];  // duplicated (w,w)
    __shared__ float w1s[32], b1s[32], b2s[64], wms[64];
    int tid = threadIdx.x;
    for (int idx = tid; idx < 2048; idx += 256) {
        float w = Wd2[idx];
        wd2s[idx] = pack2(w, w);
    }
    if (tid < 32) { w1s[tid] = Wd1[tid]; b1s[tid] = bd1[tid]; }
    if (tid < 64) { b2s[tid] = bd2[tid]; wms[tid] = wm[tid]; }
    __syncthreads();

    int i = blockIdx.x;
    float lx = lc[i * 3 + 0], ly = lc[i * 3 + 1], lz = lc[i * 3 + 2];
    int j0 = blockIdx.y * 512 + tid;
    int j1 = j0 + 256;

    float dx = lx - pc[j0 * 3 + 0], dy = ly - pc[j0 * 3 + 1], dz = lz - pc[j0 * 3 + 2];
    float d0 = sqrtf(dx * dx + dy * dy + dz * dz);
    dx = lx - pc[j1 * 3 + 0]; dy = ly - pc[j1 * 3 + 1]; dz = lz - pc[j1 * 3 + 2];
    float d1 = sqrtf(dx * dx + dy * dy + dz * dz);

    unsigned long long e1[32];
    #pragma unroll
    for (int k = 0; k < 32; k++) {
        float a0 = fmaxf(fmaf(d0, w1s[k], b1s[k]), 0.f);
        float a1 = fmaxf(fmaf(d1, w1s[k], b1s[k]), 0.f);
        e1[k] = pack2(a0, a1);
    }

    float m0 = 0.f, m1 = 0.f;
    for (int j2 = 0; j2 < 64; j2++) {
        float b2 = b2s[j2];
        unsigned long long accA = pack2(b2, b2);
        unsigned long long accB = pack2(0.f, 0.f);
        const ulonglong2* wr = (const ulonglong2*)(wd2s + j2 * 32);
        #pragma unroll
        for (int q = 0; q < 16; q++) {
            ulonglong2 w = wr[q];
            accA = fma2(e1[2 * q + 0], w.x, accA);
            accB = fma2(e1[2 * q + 1], w.y, accB);
        }
        float ax, ay, bx, by;
        unpack2(accA, ax, ay);
        unpack2(accB, bx, by);
        float r0 = fmaxf(ax + bx, 0.f);
        float r1 = fmaxf(ay + by, 0.f);
        float wmv = wms[j2];
        m0 = fmaf(r0, wmv, m0);
        m1 = fmaf(r1, wmv, m1);
    }
    float cst = *mc;
    M[(size_t)i * 1024 + j0] = m0 + cst;
    M[(size_t)i * 1024 + j1] = m1 + cst;
}

// ---------------- row softmax (ncols <= 1024), dst = softmax(sign*src) -------
__global__ void __launch_bounds__(256) k_softmax_row(const float* __restrict__ src,
                                                     float* __restrict__ dst,
                                                     int ncols, float sign) {
    __shared__ float buf[1024];
    int row = blockIdx.x, tid = threadIdx.x;
    const float* s = src + (size_t)row * ncols;
    float mx = -3.4e38f;
    for (int j = tid; j < ncols; j += 256) {
        float v = sign * s[j];
        buf[j] = v;
        mx = fmaxf(mx, v);
    }
    __syncthreads();
    mx = blkMax(mx);
    float sum = 0.f;
    for (int j = tid; j < ncols; j += 256) {
        float e = __expf(buf[j] - mx);
        buf[j] = e;
        sum += e;
    }
    sum = blkSum(sum);
    float inv = 1.f / sum;
    float* d = dst + (size_t)row * ncols;
    for (int j = tid; j < ncols; j += 256) d[j] = buf[j] * inv;
}

// ---------------- column softmax: swp[p][i] = softmax_i(-m[i][p]) -------------
__global__ void __launch_bounds__(256) k_softmax_col(const float* __restrict__ m,
                                                     float* __restrict__ swp) {
    __shared__ float buf[512];
    int p = blockIdx.x, tid = threadIdx.x;
    float mx = -3.4e38f;
    for (int i = tid; i < 512; i += 256) {
        float v = -m[(size_t)i * 1024 + p];
        buf[i] = v;
        mx = fmaxf(mx, v);
    }
    __syncthreads();
    mx = blkMax(mx);
    float sum = 0.f;
    for (int i = tid; i < 512; i += 256) {
        float e = __expf(buf[i] - mx);
        buf[i] = e;
        sum += e;
    }
    sum = blkSum(sum);
    float inv = 1.f / sum;
    for (int i = tid; i < 512; i += 256) swp[(size_t)p * 512 + i] = buf[i] * inv;
}

// ---------------- Y[M,128] = A[M,K] @ B[K,128], 16 rows/block -----------------
__global__ void __launch_bounds__(128) k_gemm_nn(const float* __restrict__ A,
                                                 const float* __restrict__ B,
                                                 float* __restrict__ Y, int K) {
    __shared__ __align__(16) float As[16 * 128];
    int tid = threadIdx.x, r0 = blockIdx.x * 16, c = tid;
    float acc[16];
    #pragma unroll
    for (int r = 0; r < 16; r++) acc[r] = 0.f;
    for (int kb = 0; kb < K; kb += 128) {
        __syncthreads();
        for (int idx = tid; idx < 512; idx += 128) {
            int row = idx >> 5, col4 = idx & 31;
            ((float4*)As)[idx] =
                ((const float4*)(A + (size_t)(r0 + row) * K + kb))[col4];
        }
        __syncthreads();
        #pragma unroll 4
        for (int k = 0; k < 128; k++) {
            float b = B[(size_t)(kb + k) * 128 + c];
            #pragma unroll
            for (int r = 0; r < 16; r++) acc[r] = fmaf(As[r * 128 + k], b, acc[r]);
        }
    }
    #pragma unroll
    for (int r = 0; r < 16; r++) Y[(size_t)(r0 + r) * 128 + c] = acc[r];
}

// ---------------- gate: enh = g*x + (1-g)*agg, g = sig([x,agg]@W^T + b) -------
__global__ void __launch_bounds__(128) k_gate(const float* __restrict__ X,
                                              const float* __restrict__ A,
                                              const float* __restrict__ W,
                                              const float* __restrict__ bias,
                                              float* __restrict__ Y) {
    __shared__ __align__(16) float xs[16 * 128];
    __shared__ __align__(16) float as_[16 * 128];
    int tid = threadIdx.x, r0 = blockIdx.x * 16, c = tid;
    for (int idx = tid; idx < 512; idx += 128) {
        ((float4*)xs)[idx] = ((const float4*)(X + (size_t)r0 * 128))[idx];
        ((float4*)as_)[idx] = ((const float4*)(A + (size_t)r0 * 128))[idx];
    }
    __syncthreads();
    float acc[16];
    float bv = bias[c];
    #pragma unroll
    for (int r = 0; r < 16; r++) acc[r] = bv;
    const float* w = W + (size_t)c * 256;
    #pragma unroll 4
    for (int k = 0; k < 128; k++) {
        float wv = w[k];
        #pragma unroll
        for (int r = 0; r < 16; r++) acc[r] = fmaf(xs[r * 128 + k], wv, acc[r]);
    }
    #pragma unroll 4
    for (int k = 0; k < 128; k++) {
        float wv = w[128 + k];
        #pragma unroll
        for (int r = 0; r < 16; r++) acc[r] = fmaf(as_[r * 128 + k], wv, acc[r]);
    }
    #pragma unroll
    for (int r = 0; r < 16; r++) {
        float g = 1.f / (1.f + __expf(-acc[r]));
        float xv = xs[r * 128 + c], av = as_[r * 128 + c];
        Y[(size_t)(r0 + r) * 128 + c] = g * xv + (1.f - g) * av;
    }
}

// ---------------- attention scores: S[h,i,j] = 0.25 * <q_i, k_j> --------------
// grid(nk/128, nq/32, 8), block 256.
__global__ void __launch_bounds__(256) k_scores(const float* __restrict__ Qb,
                                                const float* __restrict__ Kb,
                                                float* __restrict__ S,
                                                int nq, int nk) {
    __shared__ float Qs[32 * 16];
    __shared__ float Ks[128 * 17];
    int h = blockIdx.z, i0 = blockIdx.y * 32, jb = blockIdx.x * 128;
    int tid = threadIdx.x;
    for (int idx = tid; idx < 512; idx += 256) {
        int r = idx >> 4, d = idx & 15;
        Qs[idx] = Qb[(size_t)(i0 + r) * 384 + h * 16 + d];
    }
    for (int idx = tid; idx < 2048; idx += 256) {
        int r = idx >> 4, d = idx & 15;
        Ks[r * 17 + d] = Kb[(size_t)(jb + r) * 384 + 128 + h * 16 + d];
    }
    __syncthreads();
    int j = tid & 127, ig = tid >> 7;
    float acc[16];
    #pragma unroll
    for (int r = 0; r < 16; r++) acc[r] = 0.f;
    #pragma unroll
    for (int d = 0; d < 16; d++) {
        float kv = Ks[j * 17 + d];
        #pragma unroll
        for (int r = 0; r < 16; r++)
            acc[r] = fmaf(Qs[(ig * 16 + r) * 16 + d], kv, acc[r]);
    }
    size_t base = ((size_t)h * nq + i0 + ig * 16) * nk + jb + j;
    #pragma unroll
    for (int r = 0; r < 16; r++) S[base + (size_t)r * nk] = acc[r] * 0.25f;
}

// ---------------- AV: out[i, h*16+d] = sum_j S[h,i,j] * V[j, h*16+d] -----------
// grid(nq/32, 8), block 256.
__global__ void __launch_bounds__(256) k_av(const float* __restrict__ S,
                                            const float* __restrict__ Vb,
                                            float* __restrict__ out,
                                            int nq, int nk) {
    __shared__ __align__(16) float Ss[32 * 136];
    __shared__ __align__(16) float VsT[16 * 136];
    int h = blockIdx.y, i0 = blockIdx.x * 32;
    int tid = threadIdx.x;
    int d = tid & 15, ig = tid >> 4;
    float acc0 = 0.f, acc1 = 0.f;
    for (int jb = 0; jb < nk; jb += 128) {
        __syncthreads();
        for (int idx = tid; idx < 4096; idx += 256) {
            int row = idx >> 7, col = idx & 127;
            Ss[row * 136 + col] = S[((size_t)h * nq + i0 + row) * nk + jb + col];
        }
        for (int idx = tid; idx < 2048; idx += 256) {
            int j = idx >> 4, dd = idx & 15;
            VsT[dd * 136 + j] = Vb[(size_t)(jb + j) * 384 + 256 + h * 16 + dd];
        }
        __syncthreads();
        const float4* vrow = (const float4*)(VsT + d * 136);
        const float4* s0 = (const float4*)(Ss + (ig * 2 + 0) * 136);
        const float4* s1 = (const float4*)(Ss + (ig * 2 + 1) * 136);
        #pragma unroll
        for (int q = 0; q < 32; q++) {
            float4 v = vrow[q], a = s0[q], b = s1[q];
            acc0 = fmaf(a.x, v.x, acc0); acc0 = fmaf(a.y, v.y, acc0);
            acc0 = fmaf(a.z, v.z, acc0); acc0 = fmaf(a.w, v.w, acc0);
            acc1 = fmaf(b.x, v.x, acc1); acc1 = fmaf(b.y, v.y, acc1);
            acc1 = fmaf(b.z, v.z, acc1); acc1 = fmaf(b.w, v.w, acc1);
        }
    }
    out[(size_t)(i0 + ig * 2 + 0) * 128 + h * 16 + d] = acc0;
    out[(size_t)(i0 + ig * 2 + 1) * 128 + h * 16 + d] = acc1;
}

// ---------------- add + LayerNorm, one row per block (128 threads) ------------
__global__ void __launch_bounds__(128) k_addln(const float* __restrict__ Xe,
                                               const float* __restrict__ Ap,
                                               const float* __restrict__ g,
                                               const float* __restrict__ b,
                                               float* __restrict__ out) {
    int row = blockIdx.x, c = threadIdx.x;
    float t = Xe[(size_t)row * 128 + c] + Ap[(size_t)row * 128 + c];
    float mean = blkSum(t) * (1.f / 128.f);
    float dv = t - mean;
    float var = blkSum(dv * dv) * (1.f / 128.f);
    out[(size_t)row * 128 + c] = dv * rsqrtf(var + 1e-5f) * g[c] + b[c];
}

// ---------------- launch ------------------------------------------------------
extern "C" void kernel_launch(void* const* d_in, const int* in_sizes, int n_in,
                              void* d_out, int out_size) {
    const float* lf   = (const float*)d_in[0];
    const float* pf   = (const float*)d_in[1];
    const float* lc   = (const float*)d_in[2];
    const float* pc   = (const float*)d_in[3];
    const float* Wl   = (const float*)d_in[4];
    const float* bl   = (const float*)d_in[5];
    const float* Wp   = (const float*)d_in[6];
    const float* bp   = (const float*)d_in[7];
    const float* Wd1  = (const float*)d_in[8];
    const float* bd1  = (const float*)d_in[9];
    const float* Wd2  = (const float*)d_in[10];
    const float* bd2  = (const float*)d_in[11];
    const float* Wd3  = (const float*)d_in[12];
    const float* bd3  = (const float*)d_in[13];
    const float* Wgl  = (const float*)d_in[14];
    const float* bgl  = (const float*)d_in[15];
    const float* Wgp  = (const float*)d_in[16];
    const float* bgp  = (const float*)d_in[17];
    const float* Wqkv = (const float*)d_in[18];
    const float* bqkv = (const float*)d_in[19];
    const float* Wo   = (const float*)d_in[20];
    const float* bo   = (const float*)d_in[21];
    const float* g_l  = (const float*)d_in[22];
    const float* be_l = (const float*)d_in[23];
    const float* g_p  = (const float*)d_in[24];
    const float* be_p = (const float*)d_in[25];
    float* out = (float*)d_out;

    float* SB = nullptr;
    cudaGetSymbolAddress((void**)&SB, g_scratch);
    float* s_lig  = SB + OFF_LIG;
    float* s_poc  = SB + OFF_POC;
    float* s_m    = SB + OFF_M;
    float* s_swl  = SB + OFF_SWL;
    float* s_swp  = SB + OFF_SWP;
    float* s_aggl = SB + OFF_AGGL;
    float* s_aggp = SB + OFF_AGGP;
    float* s_lige = SB + OFF_LIGE;
    float* s_poce = SB + OFF_POCE;
    float* s_qkvl = SB + OFF_QKVL;
    float* s_qkvp = SB + OFF_QKVP;
    float* s_sl   = SB + OFF_SL;
    float* s_sp   = SB + OFF_SP;
    float* s_attl = SB + OFF_ATTL;
    float* s_attp = SB + OFF_ATTP;
    float* s_apl  = SB + OFF_APL;
    float* s_app  = SB + OFF_APP;
    float* s_wm   = SB + OFF_WM;
    float* s_mc   = SB + OFF_MC;

    // prep + input projections
    k_prep<<<1, 128>>>(Wd3, bd3, s_wm, s_mc);
    k_linear<<<dim3(32, 1), 128>>>(lf, Wl, bl, s_lig, 128, 128);
    k_linear<<<dim3(64, 1), 128>>>(pf, Wp, bp, s_poc, 128, 128);

    // pairwise distance MLP -> m (mean-folded last layer)
    k_pair<<<dim3(512, 2), 256>>>(lc, pc, Wd1, bd1, Wd2, bd2, s_wm, s_mc, s_m);

    // spatial softmaxes + aggregation + gates
    k_softmax_row<<<512, 256>>>(s_m, s_swl, 1024, -1.f);
    k_softmax_col<<<1024, 256>>>(s_m, s_swp);
    k_gemm_nn<<<32, 128>>>(s_swl, s_poc, s_aggl, 1024);
    k_gemm_nn<<<64, 128>>>(s_swp, s_lig, s_aggp, 512);
    k_gate<<<32, 128>>>(s_lig, s_aggl, Wgl, bgl, s_lige);
    k_gate<<<64, 128>>>(s_poc, s_aggp, Wgp, bgp, s_poce);

    // qkv projections (shared weights, both tensors)
    k_linear<<<dim3(32, 3), 128>>>(s_lige, Wqkv, bqkv, s_qkvl, 128, 384);
    k_linear<<<dim3(64, 3), 128>>>(s_poce, Wqkv, bqkv, s_qkvp, 128, 384);

    // cross attention: lig queries / poc kv, and poc queries / lig kv
    k_scores<<<dim3(8, 16, 8), 256>>>(s_qkvl, s_qkvp, s_sl, 512, 1024);
    k_scores<<<dim3(4, 32, 8), 256>>>(s_qkvp, s_qkvl, s_sp, 1024, 512);
    k_softmax_row<<<4096, 256>>>(s_sl, s_sl, 1024, 1.f);
    k_softmax_row<<<8192, 256>>>(s_sp, s_sp, 512, 1.f);
    k_av<<<dim3(16, 8), 256>>>(s_sl, s_qkvp, s_attl, 512, 1024);
    k_av<<<dim3(32, 8), 256>>>(s_sp, s_qkvl, s_attp, 1024, 512);

    // output projection + residual + layernorm
    k_linear<<<dim3(32, 1), 128>>>(s_attl, Wo, bo, s_apl, 128, 128);
    k_linear<<<dim3(64, 1), 128>>>(s_attp, Wo, bo, s_app, 128, 128);
    k_addln<<<512, 128>>>(s_lige, s_apl, g_l, be_l, out);
    k_addln<<<1024, 128>>>(s_poce, s_app, g_p, be_p, out + 512 * 128);
}

// round 6
// speedup vs baseline: 1.1063x; 1.1063x over previous
#include <cuda_runtime.h>
#include <math.h>

// ---------------- scratch (device globals; no allocation allowed) ----------
#define OFF_LIG     0           // 512*128
#define OFF_POC     65536       // 1024*128
#define OFF_M       196608      // 512*1024
#define OFF_MT      720896      // 1024*512
#define OFF_SWL     1245184     // 512*1024
#define OFF_SWP     1769472     // 1024*512
#define OFF_AGGL    2293760     // 512*128
#define OFF_AGGP    2359296     // 1024*128
#define OFF_LIGE    2490368     // 512*128
#define OFF_POCE    2555904     // 1024*128
#define OFF_QKVL    2686976     // 512*384
#define OFF_QKVP    2883584     // 1024*384
#define OFF_ATTL    3276800     // 512*128
#define OFF_ATTP    3342336     // 1024*128
#define OFF_WM      3473408     // 64
#define OFF_MC      3473472     // 1 (padded)
#define SCRATCH_FLOATS 3473536

__device__ float g_scratch[SCRATCH_FLOATS];

// ---------------- f32x2 packed helpers -------------------------------------
__device__ __forceinline__ unsigned long long pack2(float x, float y) {
    unsigned long long r;
    asm("mov.b64 %0, {%1, %2};" : "=l"(r) : "f"(x), "f"(y));
    return r;
}
__device__ __forceinline__ void unpack2(unsigned long long v, float& x, float& y) {
    asm("mov.b64 {%0, %1}, %2;" : "=f"(x), "=f"(y) : "l"(v));
}
__device__ __forceinline__ unsigned long long fma2(unsigned long long a,
                                                   unsigned long long b,
                                                   unsigned long long c) {
    unsigned long long d;
    asm("fma.rn.f32x2 %0, %1, %2, %3;" : "=l"(d) : "l"(a), "l"(b), "l"(c));
    return d;
}

// ---------------- block reductions ------------------------------------------
__device__ __forceinline__ float blkSum(float v) {
    __shared__ float sm[8];
    #pragma unroll
    for (int o = 16; o > 0; o >>= 1) v += __shfl_xor_sync(0xffffffffu, v, o);
    unsigned nw = blockDim.x >> 5;
    if ((threadIdx.x & 31) == 0) sm[threadIdx.x >> 5] = v;
    __syncthreads();
    float r = 0.f;
    for (unsigned w = 0; w < nw; w++) r += sm[w];
    __syncthreads();
    return r;
}
__device__ __forceinline__ float blkMax(float v) {
    __shared__ float sm2[8];
    #pragma unroll
    for (int o = 16; o > 0; o >>= 1) v = fmaxf(v, __shfl_xor_sync(0xffffffffu, v, o));
    unsigned nw = blockDim.x >> 5;
    if ((threadIdx.x & 31) == 0) sm2[threadIdx.x >> 5] = v;
    __syncthreads();
    float r = -3.4e38f;
    for (unsigned w = 0; w < nw; w++) r = fmaxf(r, sm2[w]);
    __syncthreads();
    return r;
}

// ---------------- prep: column-means of Wd3, mean of bd3 --------------------
__global__ void k_prep(const float* __restrict__ Wd3, const float* __restrict__ bd3,
                       float* __restrict__ wm, float* __restrict__ mc) {
    int t = threadIdx.x;
    if (t < 64) {
        float s = 0.f;
        for (int i = 0; i < 128; i++) s += Wd3[i * 64 + t];
        wm[t] = s * (1.f / 128.f);
    }
    if (t == 0) {
        float s = 0.f;
        for (int i = 0; i < 128; i++) s += bd3[i];
        *mc = s * (1.f / 128.f);
    }
}

// ---------------- Y[M,N] = X[M,K] @ W[N,K]^T + b, 16 rows/block --------------
__global__ void __launch_bounds__(128) k_linear(const float* __restrict__ X,
                                                const float* __restrict__ W,
                                                const float* __restrict__ bias,
                                                float* __restrict__ Y,
                                                int K, int N) {
    __shared__ __align__(16) float Xs[16 * 128];
    int tid = threadIdx.x;
    int r0 = blockIdx.x * 16;
    int c = blockIdx.y * 128 + tid;
    int nf4 = 4 * K;
    const float4* xsrc = (const float4*)(X + (size_t)r0 * K);
    float4* xdst = (float4*)Xs;
    for (int idx = tid; idx < nf4; idx += 128) xdst[idx] = xsrc[idx];
    __syncthreads();
    float acc[16];
    float bv = bias[c];
    #pragma unroll
    for (int r = 0; r < 16; r++) acc[r] = bv;
    const float* w = W + (size_t)c * K;
    #pragma unroll 4
    for (int k = 0; k < K; k++) {
        float wv = w[k];
        #pragma unroll
        for (int r = 0; r < 16; r++) acc[r] = fmaf(Xs[r * K + k], wv, acc[r]);
    }
    #pragma unroll
    for (int r = 0; r < 16; r++) Y[(size_t)(r0 + r) * N + c] = acc[r];
}

// ---------------- pair kernel: m[i][j] ---------------------------------------
// grid(512, 2), block 256. Each thread does 2 pocket indices, packed f32x2,
// 4 independent fma2 accumulator chains per j2 for ILP.
__global__ void __launch_bounds__(256) k_pair(const float* __restrict__ lc,
                                              const float* __restrict__ pc,
                                              const float* __restrict__ Wd1,
                                              const float* __restrict__ bd1,
                                              const float* __restrict__ Wd2,
                                              const float* __restrict__ bd2,
                                              const float* __restrict__ wm,
                                              const float* __restrict__ mc,
                                              float* __restrict__ M) {
    __shared__ __align__(16) unsigned long long wd2s[64 * 32];  // duplicated (w,w)
    __shared__ float w1s[32], b1s[32], b2s[64], wms[64];
    int tid = threadIdx.x;
    for (int idx = tid; idx < 2048; idx += 256) {
        float w = Wd2[idx];
        wd2s[idx] = pack2(w, w);
    }
    if (tid < 32) { w1s[tid] = Wd1[tid]; b1s[tid] = bd1[tid]; }
    if (tid < 64) { b2s[tid] = bd2[tid]; wms[tid] = wm[tid]; }
    __syncthreads();

    int i = blockIdx.x;
    float lx = lc[i * 3 + 0], ly = lc[i * 3 + 1], lz = lc[i * 3 + 2];
    int j0 = blockIdx.y * 512 + tid;
    int j1 = j0 + 256;

    float dx = lx - pc[j0 * 3 + 0], dy = ly - pc[j0 * 3 + 1], dz = lz - pc[j0 * 3 + 2];
    float d0 = sqrtf(dx * dx + dy * dy + dz * dz);
    dx = lx - pc[j1 * 3 + 0]; dy = ly - pc[j1 * 3 + 1]; dz = lz - pc[j1 * 3 + 2];
    float d1 = sqrtf(dx * dx + dy * dy + dz * dz);

    unsigned long long e1[32];
    #pragma unroll
    for (int k = 0; k < 32; k++) {
        float a0 = fmaxf(fmaf(d0, w1s[k], b1s[k]), 0.f);
        float a1 = fmaxf(fmaf(d1, w1s[k], b1s[k]), 0.f);
        e1[k] = pack2(a0, a1);
    }

    float m0 = 0.f, m1 = 0.f;
    #pragma unroll 2
    for (int j2 = 0; j2 < 64; j2++) {
        float b2 = b2s[j2];
        unsigned long long a0 = pack2(b2, b2);
        unsigned long long a1 = pack2(0.f, 0.f);
        unsigned long long a2 = a1, a3 = a1;
        const ulonglong2* wr = (const ulonglong2*)(wd2s + j2 * 32);
        #pragma unroll
        for (int q = 0; q < 8; q++) {
            ulonglong2 wA = wr[2 * q + 0];
            ulonglong2 wB = wr[2 * q + 1];
            a0 = fma2(e1[4 * q + 0], wA.x, a0);
            a1 = fma2(e1[4 * q + 1], wA.y, a1);
            a2 = fma2(e1[4 * q + 2], wB.x, a2);
            a3 = fma2(e1[4 * q + 3], wB.y, a3);
        }
        float x0, y0, x1, y1, x2, y2, x3, y3;
        unpack2(a0, x0, y0); unpack2(a1, x1, y1);
        unpack2(a2, x2, y2); unpack2(a3, x3, y3);
        float r0 = fmaxf((x0 + x1) + (x2 + x3), 0.f);
        float r1 = fmaxf((y0 + y1) + (y2 + y3), 0.f);
        float wmv = wms[j2];
        m0 = fmaf(r0, wmv, m0);
        m1 = fmaf(r1, wmv, m1);
    }
    float cst = *mc;
    M[(size_t)i * 1024 + j0] = m0 + cst;
    M[(size_t)i * 1024 + j1] = m1 + cst;
}

// ---------------- transpose 512x1024 -> 1024x512 -----------------------------
__global__ void __launch_bounds__(256) k_transpose(const float* __restrict__ M,
                                                   float* __restrict__ MT) {
    __shared__ float t[32][33];
    int bx = blockIdx.x * 32, by = blockIdx.y * 32;
    int tx = threadIdx.x, ty = threadIdx.y;
    #pragma unroll
    for (int k = 0; k < 4; k++)
        t[ty + 8 * k][tx] = M[(size_t)(by + ty + 8 * k) * 1024 + bx + tx];
    __syncthreads();
    #pragma unroll
    for (int k = 0; k < 4; k++)
        MT[(size_t)(bx + ty + 8 * k) * 512 + by + tx] = t[tx][ty + 8 * k];
}

// ---------------- row softmax (ncols <= 1024), dst = softmax(sign*src) -------
__global__ void __launch_bounds__(256) k_softmax_row(const float* __restrict__ src,
                                                     float* __restrict__ dst,
                                                     int ncols, float sign) {
    __shared__ float buf[1024];
    int row = blockIdx.x, tid = threadIdx.x;
    const float* s = src + (size_t)row * ncols;
    float mx = -3.4e38f;
    for (int j = tid; j < ncols; j += 256) {
        float v = sign * s[j];
        buf[j] = v;
        mx = fmaxf(mx, v);
    }
    __syncthreads();
    mx = blkMax(mx);
    float sum = 0.f;
    for (int j = tid; j < ncols; j += 256) {
        float e = __expf(buf[j] - mx);
        buf[j] = e;
        sum += e;
    }
    sum = blkSum(sum);
    float inv = 1.f / sum;
    float* d = dst + (size_t)row * ncols;
    for (int j = tid; j < ncols; j += 256) d[j] = buf[j] * inv;
}

// ---------------- Y[M,128] = A[M,K] @ B[K,128], 16 rows/block -----------------
__global__ void __launch_bounds__(128) k_gemm_nn(const float* __restrict__ A,
                                                 const float* __restrict__ B,
                                                 float* __restrict__ Y, int K) {
    __shared__ __align__(16) float As[16 * 128];
    int tid = threadIdx.x, r0 = blockIdx.x * 16, c = tid;
    float acc[16];
    #pragma unroll
    for (int r = 0; r < 16; r++) acc[r] = 0.f;
    for (int kb = 0; kb < K; kb += 128) {
        __syncthreads();
        for (int idx = tid; idx < 512; idx += 128) {
            int row = idx >> 5, col4 = idx & 31;
            ((float4*)As)[idx] =
                ((const float4*)(A + (size_t)(r0 + row) * K + kb))[col4];
        }
        __syncthreads();
        #pragma unroll 4
        for (int k = 0; k < 128; k++) {
            float b = B[(size_t)(kb + k) * 128 + c];
            #pragma unroll
            for (int r = 0; r < 16; r++) acc[r] = fmaf(As[r * 128 + k], b, acc[r]);
        }
    }
    #pragma unroll
    for (int r = 0; r < 16; r++) Y[(size_t)(r0 + r) * 128 + c] = acc[r];
}

// ---------------- gate: enh = g*x + (1-g)*agg, g = sig([x,agg]@W^T + b) -------
__global__ void __launch_bounds__(128) k_gate(const float* __restrict__ X,
                                              const float* __restrict__ A,
                                              const float* __restrict__ W,
                                              const float* __restrict__ bias,
                                              float* __restrict__ Y) {
    __shared__ __align__(16) float xs[16 * 128];
    __shared__ __align__(16) float as_[16 * 128];
    int tid = threadIdx.x, r0 = blockIdx.x * 16, c = tid;
    for (int idx = tid; idx < 512; idx += 128) {
        ((float4*)xs)[idx] = ((const float4*)(X + (size_t)r0 * 128))[idx];
        ((float4*)as_)[idx] = ((const float4*)(A + (size_t)r0 * 128))[idx];
    }
    __syncthreads();
    float acc[16];
    float bv = bias[c];
    #pragma unroll
    for (int r = 0; r < 16; r++) acc[r] = bv;
    const float* w = W + (size_t)c * 256;
    #pragma unroll 4
    for (int k = 0; k < 128; k++) {
        float wv = w[k];
        #pragma unroll
        for (int r = 0; r < 16; r++) acc[r] = fmaf(xs[r * 128 + k], wv, acc[r]);
    }
    #pragma unroll 4
    for (int k = 0; k < 128; k++) {
        float wv = w[128 + k];
        #pragma unroll
        for (int r = 0; r < 16; r++) acc[r] = fmaf(as_[r * 128 + k], wv, acc[r]);
    }
    #pragma unroll
    for (int r = 0; r < 16; r++) {
        float g = 1.f / (1.f + __expf(-acc[r]));
        float xv = xs[r * 128 + c], av = as_[r * 128 + c];
        Y[(size_t)(r0 + r) * 128 + c] = g * xv + (1.f - g) * av;
    }
}

// ---------------- flash attention: warp-per-query, online softmax -------------
// grid(nq/16, 8), block 512. Qb/KVb are qkv buffers [*,384]; q at col h*16,
// k at 128+h*16, v at 256+h*16. out[i, h*16+d] = softmax(qk/4) @ v.
__global__ void __launch_bounds__(512) k_flash(const float* __restrict__ Qb,
                                               const float* __restrict__ KVb,
                                               float* __restrict__ out,
                                               int nk) {
    __shared__ __align__(16) float4 Ks[128 * 5];  // padded pitch 5 float4
    __shared__ __align__(16) float4 Vs[128 * 5];
    int h = blockIdx.y;
    int tid = threadIdx.x;
    int w = tid >> 5, lane = tid & 31;
    int i = blockIdx.x * 16 + w;

    const float* qp = Qb + (size_t)i * 384 + h * 16;
    float4 q0 = ((const float4*)qp)[0];
    float4 q1 = ((const float4*)qp)[1];
    float4 q2 = ((const float4*)qp)[2];
    float4 q3 = ((const float4*)qp)[3];

    float m = -3.4e38f, l = 0.f;
    float acc[16];
    #pragma unroll
    for (int d = 0; d < 16; d++) acc[d] = 0.f;

    int jload = tid >> 2, cload = tid & 3;
    const float* kbase = KVb + (size_t)jload * 384 + 128 + h * 16 + cload * 4;

    for (int jb = 0; jb < nk; jb += 128) {
        __syncthreads();
        Ks[jload * 5 + cload] = *(const float4*)(kbase + (size_t)jb * 384);
        Vs[jload * 5 + cload] = *(const float4*)(kbase + (size_t)jb * 384 + 128);
        __syncthreads();

        float s[4];
        #pragma unroll
        for (int jj = 0; jj < 4; jj++) {
            const float4* kr = Ks + (jj * 32 + lane) * 5;
            float4 k0 = kr[0], k1 = kr[1], k2 = kr[2], k3 = kr[3];
            float t = q0.x * k0.x;
            t = fmaf(q0.y, k0.y, t); t = fmaf(q0.z, k0.z, t); t = fmaf(q0.w, k0.w, t);
            t = fmaf(q1.x, k1.x, t); t = fmaf(q1.y, k1.y, t);
            t = fmaf(q1.z, k1.z, t); t = fmaf(q1.w, k1.w, t);
            t = fmaf(q2.x, k2.x, t); t = fmaf(q2.y, k2.y, t);
            t = fmaf(q2.z, k2.z, t); t = fmaf(q2.w, k2.w, t);
            t = fmaf(q3.x, k3.x, t); t = fmaf(q3.y, k3.y, t);
            t = fmaf(q3.z, k3.z, t); t = fmaf(q3.w, k3.w, t);
            s[jj] = t * 0.25f;
        }
        float tmax = fmaxf(fmaxf(s[0], s[1]), fmaxf(s[2], s[3]));
        #pragma unroll
        for (int o = 16; o > 0; o >>= 1)
            tmax = fmaxf(tmax, __shfl_xor_sync(0xffffffffu, tmax, o));
        float mnew = fmaxf(m, tmax);
        float corr = __expf(m - mnew);
        m = mnew;
        l *= corr;
        #pragma unroll
        for (int d = 0; d < 16; d++) acc[d] *= corr;
        #pragma unroll
        for (int jj = 0; jj < 4; jj++) {
            float p = __expf(s[jj] - m);
            l += p;
            const float4* vr = Vs + (jj * 32 + lane) * 5;
            float4 v0 = vr[0], v1 = vr[1], v2 = vr[2], v3 = vr[3];
            acc[0]  = fmaf(p, v0.x, acc[0]);  acc[1]  = fmaf(p, v0.y, acc[1]);
            acc[2]  = fmaf(p, v0.z, acc[2]);  acc[3]  = fmaf(p, v0.w, acc[3]);
            acc[4]  = fmaf(p, v1.x, acc[4]);  acc[5]  = fmaf(p, v1.y, acc[5]);
            acc[6]  = fmaf(p, v1.z, acc[6]);  acc[7]  = fmaf(p, v1.w, acc[7]);
            acc[8]  = fmaf(p, v2.x, acc[8]);  acc[9]  = fmaf(p, v2.y, acc[9]);
            acc[10] = fmaf(p, v2.z, acc[10]); acc[11] = fmaf(p, v2.w, acc[11]);
            acc[12] = fmaf(p, v3.x, acc[12]); acc[13] = fmaf(p, v3.y, acc[13]);
            acc[14] = fmaf(p, v3.z, acc[14]); acc[15] = fmaf(p, v3.w, acc[15]);
        }
    }

    // cross-lane reduction
    #pragma unroll
    for (int o = 16; o > 0; o >>= 1) l += __shfl_xor_sync(0xffffffffu, l, o);
    #pragma unroll
    for (int d = 0; d < 16; d++) {
        #pragma unroll
        for (int o = 16; o > 0; o >>= 1)
            acc[d] += __shfl_xor_sync(0xffffffffu, acc[d], o);
    }
    float val = 0.f;
    #pragma unroll
    for (int d = 0; d < 16; d++) if (lane == d) val = acc[d];
    if (lane < 16) out[(size_t)i * 128 + h * 16 + lane] = val * (1.f / l);
}

// ---------------- fused out-proj + residual + LayerNorm -----------------------
// Y = LN(R + X @ Wo^T + bo). 16 rows/block, 128 threads, K=N=128.
__global__ void __launch_bounds__(128) k_outln(const float* __restrict__ X,
                                               const float* __restrict__ W,
                                               const float* __restrict__ bias,
                                               const float* __restrict__ R,
                                               const float* __restrict__ g,
                                               const float* __restrict__ b,
                                               float* __restrict__ out) {
    __shared__ __align__(16) float Xs[16 * 128];
    __shared__ __align__(16) float T[16 * 128];
    __shared__ float mu[16], iv[16];
    int tid = threadIdx.x, r0 = blockIdx.x * 16, c = tid;
    for (int idx = tid; idx < 512; idx += 128)
        ((float4*)Xs)[idx] = ((const float4*)(X + (size_t)r0 * 128))[idx];
    __syncthreads();
    float acc[16];
    float bv = bias[c];
    #pragma unroll
    for (int r = 0; r < 16; r++) acc[r] = bv;
    const float* w = W + (size_t)c * 128;
    #pragma unroll 4
    for (int k = 0; k < 128; k++) {
        float wv = w[k];
        #pragma unroll
        for (int r = 0; r < 16; r++) acc[r] = fmaf(Xs[r * 128 + k], wv, acc[r]);
    }
    #pragma unroll
    for (int r = 0; r < 16; r++)
        T[r * 128 + c] = acc[r] + R[(size_t)(r0 + r) * 128 + c];
    __syncthreads();

    int wrp = tid >> 5, lane = tid & 31;
    #pragma unroll
    for (int rr = 0; rr < 4; rr++) {
        int r = wrp * 4 + rr;
        float t0 = T[r * 128 + lane], t1 = T[r * 128 + lane + 32];
        float t2 = T[r * 128 + lane + 64], t3 = T[r * 128 + lane + 96];
        float s = (t0 + t1) + (t2 + t3);
        #pragma unroll
        for (int o = 16; o > 0; o >>= 1) s += __shfl_xor_sync(0xffffffffu, s, o);
        float mean = s * (1.f / 128.f);
        float d0 = t0 - mean, d1 = t1 - mean, d2 = t2 - mean, d3 = t3 - mean;
        float v = (d0 * d0 + d1 * d1) + (d2 * d2 + d3 * d3);
        #pragma unroll
        for (int o = 16; o > 0; o >>= 1) v += __shfl_xor_sync(0xffffffffu, v, o);
        if (lane == 0) {
            mu[r] = mean;
            iv[r] = rsqrtf(v * (1.f / 128.f) + 1e-5f);
        }
    }
    __syncthreads();
    float gc = g[c], bc = b[c];
    #pragma unroll
    for (int r = 0; r < 16; r++) {
        float t = T[r * 128 + c];
        out[(size_t)(r0 + r) * 128 + c] = (t - mu[r]) * iv[r] * gc + bc;
    }
}

// ---------------- launch ------------------------------------------------------
extern "C" void kernel_launch(void* const* d_in, const int* in_sizes, int n_in,
                              void* d_out, int out_size) {
    const float* lf   = (const float*)d_in[0];
    const float* pf   = (const float*)d_in[1];
    const float* lc   = (const float*)d_in[2];
    const float* pc   = (const float*)d_in[3];
    const float* Wl   = (const float*)d_in[4];
    const float* bl   = (const float*)d_in[5];
    const float* Wp   = (const float*)d_in[6];
    const float* bp   = (const float*)d_in[7];
    const float* Wd1  = (const float*)d_in[8];
    const float* bd1  = (const float*)d_in[9];
    const float* Wd2  = (const float*)d_in[10];
    const float* bd2  = (const float*)d_in[11];
    const float* Wd3  = (const float*)d_in[12];
    const float* bd3  = (const float*)d_in[13];
    const float* Wgl  = (const float*)d_in[14];
    const float* bgl  = (const float*)d_in[15];
    const float* Wgp  = (const float*)d_in[16];
    const float* bgp  = (const float*)d_in[17];
    const float* Wqkv = (const float*)d_in[18];
    const float* bqkv = (const float*)d_in[19];
    const float* Wo   = (const float*)d_in[20];
    const float* bo   = (const float*)d_in[21];
    const float* g_l  = (const float*)d_in[22];
    const float* be_l = (const float*)d_in[23];
    const float* g_p  = (const float*)d_in[24];
    const float* be_p = (const float*)d_in[25];
    float* out = (float*)d_out;

    float* SB = nullptr;
    cudaGetSymbolAddress((void**)&SB, g_scratch);
    float* s_lig  = SB + OFF_LIG;
    float* s_poc  = SB + OFF_POC;
    float* s_m    = SB + OFF_M;
    float* s_mt   = SB + OFF_MT;
    float* s_swl  = SB + OFF_SWL;
    float* s_swp  = SB + OFF_SWP;
    float* s_aggl = SB + OFF_AGGL;
    float* s_aggp = SB + OFF_AGGP;
    float* s_lige = SB + OFF_LIGE;
    float* s_poce = SB + OFF_POCE;
    float* s_qkvl = SB + OFF_QKVL;
    float* s_qkvp = SB + OFF_QKVP;
    float* s_attl = SB + OFF_ATTL;
    float* s_attp = SB + OFF_ATTP;
    float* s_wm   = SB + OFF_WM;
    float* s_mc   = SB + OFF_MC;

    // prep + input projections
    k_prep<<<1, 128>>>(Wd3, bd3, s_wm, s_mc);
    k_linear<<<dim3(32, 1), 128>>>(lf, Wl, bl, s_lig, 128, 128);
    k_linear<<<dim3(64, 1), 128>>>(pf, Wp, bp, s_poc, 128, 128);

    // pairwise distance MLP -> m (mean-folded last layer)
    k_pair<<<dim3(512, 2), 256>>>(lc, pc, Wd1, bd1, Wd2, bd2, s_wm, s_mc, s_m);
    k_transpose<<<dim3(32, 16), dim3(32, 8)>>>(s_m, s_mt);

    // spatial softmaxes + aggregation + gates
    k_softmax_row<<<512, 256>>>(s_m, s_swl, 1024, -1.f);
    k_softmax_row<<<1024, 256>>>(s_mt, s_swp, 512, -1.f);
    k_gemm_nn<<<32, 128>>>(s_swl, s_poc, s_aggl, 1024);
    k_gemm_nn<<<64, 128>>>(s_swp, s_lig, s_aggp, 512);
    k_gate<<<32, 128>>>(s_lig, s_aggl, Wgl, bgl, s_lige);
    k_gate<<<64, 128>>>(s_poc, s_aggp, Wgp, bgp, s_poce);

    // qkv projections (shared weights, both tensors)
    k_linear<<<dim3(32, 3), 128>>>(s_lige, Wqkv, bqkv, s_qkvl, 128, 384);
    k_linear<<<dim3(64, 3), 128>>>(s_poce, Wqkv, bqkv, s_qkvp, 128, 384);

    // fused flash cross-attention (no materialized scores)
    k_flash<<<dim3(32, 8), 512>>>(s_qkvl, s_qkvp, s_attl, 1024);
    k_flash<<<dim3(64, 8), 512>>>(s_qkvp, s_qkvl, s_attp, 512);

    // fused output projection + residual + layernorm
    k_outln<<<32, 128>>>(s_attl, Wo, bo, s_lige, g_l, be_l, out);
    k_outln<<<64, 128>>>(s_attp, Wo, bo, s_poce, g_p, be_p, out + 512 * 128);
}

// round 7
// speedup vs baseline: 2.3474x; 2.1219x over previous
#include <cuda_runtime.h>
#include <math.h>

// ---------------- scratch (device globals; no allocation allowed) ----------
#define OFF_LIG     0           // 512*128
#define OFF_POC     65536       // 1024*128
#define OFF_M       196608      // 512*1024
#define OFF_SWL     720896      // 512*1024
#define OFF_SWP     1245184     // 1024*512
#define OFF_AGGL    1769472     // 512*128
#define OFF_AGGP    1835008     // 1024*128
#define OFF_LIGE    1966080     // 512*128
#define OFF_POCE    2031616     // 1024*128
#define OFF_QKVL    2162688     // 512*384
#define OFF_QKVP    2359296     // 1024*384
#define OFF_ATTL    2752512     // 512*128
#define OFF_ATTP    2818048     // 1024*128
#define OFF_TAB     2949120     // 4096
#define SCRATCH_FLOATS 2953216

__device__ float g_scratch[SCRATCH_FLOATS];

#define TAB_N 4096
#define D_MAX 35.0f

// ---------------- block reductions ------------------------------------------
__device__ __forceinline__ float blkSum(float v) {
    __shared__ float sm[8];
    #pragma unroll
    for (int o = 16; o > 0; o >>= 1) v += __shfl_xor_sync(0xffffffffu, v, o);
    unsigned nw = blockDim.x >> 5;
    if ((threadIdx.x & 31) == 0) sm[threadIdx.x >> 5] = v;
    __syncthreads();
    float r = 0.f;
    for (unsigned w = 0; w < nw; w++) r += sm[w];
    __syncthreads();
    return r;
}
__device__ __forceinline__ float blkMax(float v) {
    __shared__ float sm2[8];
    #pragma unroll
    for (int o = 16; o > 0; o >>= 1) v = fmaxf(v, __shfl_xor_sync(0xffffffffu, v, o));
    unsigned nw = blockDim.x >> 5;
    if ((threadIdx.x & 31) == 0) sm2[threadIdx.x >> 5] = v;
    __syncthreads();
    float r = -3.4e38f;
    for (unsigned w = 0; w < nw; w++) r = fmaxf(r, sm2[w]);
    __syncthreads();
    return r;
}

// ---------------- table build: tab[i] = m(d_i), d_i = i*D_MAX/(TAB_N-1) ------
// m(d) = sum_j wm_j * relu( sum_k Wd2[j][k]*relu(d*Wd1[k]+bd1[k]) + bd2[j] ) + mean(bd3)
// wm_j = mean_i Wd3[i][j]. grid 32, block 128.
__global__ void __launch_bounds__(128) k_table(const float* __restrict__ Wd1,
                                               const float* __restrict__ bd1,
                                               const float* __restrict__ Wd2,
                                               const float* __restrict__ bd2,
                                               const float* __restrict__ Wd3,
                                               const float* __restrict__ bd3,
                                               float* __restrict__ tab) {
    __shared__ __align__(16) float Wd2s[2048];
    __shared__ float w1s[32], b1s[32], b2s[64], wms[64], mcs;
    int tid = threadIdx.x;
    for (int idx = tid; idx < 2048; idx += 128) Wd2s[idx] = Wd2[idx];
    if (tid < 32) { w1s[tid] = Wd1[tid]; b1s[tid] = bd1[tid]; }
    if (tid >= 32 && tid < 96) b2s[tid - 32] = bd2[tid - 32];
    if (tid < 64) {
        float s = 0.f;
        for (int i = 0; i < 128; i++) s += Wd3[i * 64 + tid];
        wms[tid] = s * (1.f / 128.f);
    }
    if (tid == 127) {
        float s = 0.f;
        for (int i = 0; i < 128; i++) s += bd3[i];
        mcs = s * (1.f / 128.f);
    }
    __syncthreads();

    int idx = blockIdx.x * 128 + tid;
    float d = (float)idx * (D_MAX / (float)(TAB_N - 1));
    float h1[32];
    #pragma unroll
    for (int k = 0; k < 32; k++) h1[k] = fmaxf(fmaf(d, w1s[k], b1s[k]), 0.f);
    float mval = mcs;
    #pragma unroll 1
    for (int j = 0; j < 64; j++) {
        const float4* wr = (const float4*)(Wd2s + j * 32);
        float a0 = 0.f, a1 = 0.f, a2 = 0.f, a3 = 0.f;
        #pragma unroll
        for (int q = 0; q < 8; q++) {
            float4 w = wr[q];
            a0 = fmaf(w.x, h1[4 * q + 0], a0);
            a1 = fmaf(w.y, h1[4 * q + 1], a1);
            a2 = fmaf(w.z, h1[4 * q + 2], a2);
            a3 = fmaf(w.w, h1[4 * q + 3], a3);
        }
        float pre = b2s[j] + ((a0 + a1) + (a2 + a3));
        mval = fmaf(fmaxf(pre, 0.f), wms[j], mval);
    }
    tab[idx] = mval;
}

// ---------------- merged input projections (lig | poc) -----------------------
// grid 96 (32 lig + 64 poc), block 128. 16 rows/block, K=N=128.
__global__ void __launch_bounds__(128) k_inproj(const float* __restrict__ lf,
                                                const float* __restrict__ pf,
                                                const float* __restrict__ Wl,
                                                const float* __restrict__ bl,
                                                const float* __restrict__ Wp,
                                                const float* __restrict__ bp,
                                                float* __restrict__ lig,
                                                float* __restrict__ poc) {
    __shared__ __align__(16) float Xs[16 * 128];
    int tid = threadIdx.x, bx = blockIdx.x;
    const float* X; const float* W; const float* B; float* Y; int r0;
    if (bx < 32) { X = lf; W = Wl; B = bl; Y = lig; r0 = bx * 16; }
    else         { X = pf; W = Wp; B = bp; Y = poc; r0 = (bx - 32) * 16; }
    const float4* xsrc = (const float4*)(X + (size_t)r0 * 128);
    for (int idx = tid; idx < 512; idx += 128) ((float4*)Xs)[idx] = xsrc[idx];
    __syncthreads();
    float acc[16];
    float bv = B[tid];
    #pragma unroll
    for (int r = 0; r < 16; r++) acc[r] = bv;
    const float* w = W + (size_t)tid * 128;
    #pragma unroll 4
    for (int k = 0; k < 128; k++) {
        float wv = w[k];
        #pragma unroll
        for (int r = 0; r < 16; r++) acc[r] = fmaf(Xs[r * 128 + k], wv, acc[r]);
    }
    #pragma unroll
    for (int r = 0; r < 16; r++) Y[(size_t)(r0 + r) * 128 + tid] = acc[r];
}

// ---------------- pair + row softmax: m rows and swl rows --------------------
// grid 128 (4 lig rows each), block 256. Table lookup replaces the MLP.
__global__ void __launch_bounds__(256) k_pairsoft(const float* __restrict__ lc,
                                                  const float* __restrict__ pc,
                                                  const float* __restrict__ tab,
                                                  float* __restrict__ M,
                                                  float* __restrict__ swl) {
    __shared__ float tabs[TAB_N];
    __shared__ float pcs[3072];
    __shared__ float row[4096];
    int tid = threadIdx.x;
    for (int idx = tid; idx < TAB_N; idx += 256) tabs[idx] = tab[idx];
    for (int idx = tid; idx < 3072; idx += 256) pcs[idx] = pc[idx];
    __syncthreads();

    const float invh = (float)(TAB_N - 1) / D_MAX;
    #pragma unroll 1
    for (int r = 0; r < 4; r++) {
        int i = blockIdx.x * 4 + r;
        float lx = lc[i * 3 + 0], ly = lc[i * 3 + 1], lz = lc[i * 3 + 2];
        float mx = -3.4e38f;
        #pragma unroll
        for (int jj = 0; jj < 4; jj++) {
            int j = jj * 256 + tid;
            float dx = lx - pcs[j * 3 + 0];
            float dy = ly - pcs[j * 3 + 1];
            float dz = lz - pcs[j * 3 + 2];
            float d = sqrtf(fmaf(dx, dx, fmaf(dy, dy, dz * dz)));
            float t = d * invh;
            int i0 = min((int)t, TAB_N - 2);
            float f = t - (float)i0;
            float v0 = tabs[i0], v1 = tabs[i0 + 1];
            float v = fmaf(f, v1 - v0, v0);
            row[r * 1024 + j] = v;
            M[(size_t)i * 1024 + j] = v;
            mx = fmaxf(mx, -v);
        }
        mx = blkMax(mx);
        float s = 0.f;
        #pragma unroll
        for (int jj = 0; jj < 4; jj++) {
            int j = jj * 256 + tid;
            float e = __expf(-row[r * 1024 + j] - mx);
            row[r * 1024 + j] = e;
            s += e;
        }
        s = blkSum(s);
        float inv = 1.f / s;
        #pragma unroll
        for (int jj = 0; jj < 4; jj++) {
            int j = jj * 256 + tid;
            swl[(size_t)i * 1024 + j] = row[r * 1024 + j] * inv;
        }
    }
}

// ---------------- transpose + column softmax: swp[p][i]=softmax_i(-m[i][p]) --
// grid 64 (16 p each), block 256.
__global__ void __launch_bounds__(256) k_transsoft(const float* __restrict__ M,
                                                   float* __restrict__ swp) {
    __shared__ float sm[16 * 513];
    __shared__ float invp[16];
    int tid = threadIdx.x;
    int p0 = blockIdx.x * 16;
    int pl = tid & 15, ig = tid >> 4;
    // load 512 x 16 tile, transposed into sm[p][i]
    #pragma unroll 4
    for (int pass = 0; pass < 32; pass++) {
        int i = pass * 16 + ig;
        sm[pl * 513 + i] = M[(size_t)i * 1024 + p0 + pl];
    }
    __syncthreads();
    // softmax per p-row: 16 lanes per row
    int p = tid >> 4, t16 = tid & 15;
    float mx = -3.4e38f;
    for (int i = t16; i < 512; i += 16) mx = fmaxf(mx, -sm[p * 513 + i]);
    #pragma unroll
    for (int o = 8; o > 0; o >>= 1) mx = fmaxf(mx, __shfl_xor_sync(0xffffffffu, mx, o));
    float s = 0.f;
    for (int i = t16; i < 512; i += 16) {
        float e = __expf(-sm[p * 513 + i] - mx);
        sm[p * 513 + i] = e;
        s += e;
    }
    #pragma unroll
    for (int o = 8; o > 0; o >>= 1) s += __shfl_xor_sync(0xffffffffu, s, o);
    if (t16 == 0) invp[p] = 1.f / s;
    __syncthreads();
    for (int idx = tid; idx < 8192; idx += 256) {
        int pp = idx >> 9, i = idx & 511;
        swp[(size_t)(p0 + pp) * 512 + i] = sm[pp * 513 + i] * invp[pp];
    }
}

// ---------------- merged agg GEMMs: aggl = swl@poc, aggp = swp@lig -----------
// grid 192 (64 lig-blocks of 8 rows + 128 poc-blocks), block 256.
// Thread = (col c, K-half). A staged k-major [K][8] for LDS.128 broadcast.
__global__ void __launch_bounds__(256) k_agg(const float* __restrict__ swl,
                                             const float* __restrict__ swp,
                                             const float* __restrict__ poc,
                                             const float* __restrict__ lig,
                                             float* __restrict__ aggl,
                                             float* __restrict__ aggp) {
    __shared__ __align__(16) float As[1024 * 8];
    int tid = threadIdx.x, bx = blockIdx.x;
    const float* A; const float* B; float* Y; int r0, K, kbits;
    if (bx < 64) { A = swl; B = poc; Y = aggl; r0 = bx * 8; K = 1024; kbits = 10; }
    else         { A = swp; B = lig; Y = aggp; r0 = (bx - 64) * 8; K = 512; kbits = 9; }
    for (int idx = tid; idx < 8 * K; idx += 256) {
        int r = idx >> kbits, k = idx & (K - 1);
        As[k * 8 + r] = A[(size_t)(r0 + r) * K + k];
    }
    __syncthreads();
    int c = tid & 127, half = tid >> 7;
    int khalf = K >> 1;
    int ks = half * khalf;
    float acc[8];
    #pragma unroll
    for (int r = 0; r < 8; r++) acc[r] = 0.f;
    const float4* As4 = (const float4*)As;
    #pragma unroll 4
    for (int kk = 0; kk < khalf; kk++) {
        int k = ks + kk;
        float b = B[(size_t)k * 128 + c];
        float4 a0 = As4[k * 2 + 0], a1 = As4[k * 2 + 1];
        acc[0] = fmaf(a0.x, b, acc[0]); acc[1] = fmaf(a0.y, b, acc[1]);
        acc[2] = fmaf(a0.z, b, acc[2]); acc[3] = fmaf(a0.w, b, acc[3]);
        acc[4] = fmaf(a1.x, b, acc[4]); acc[5] = fmaf(a1.y, b, acc[5]);
        acc[6] = fmaf(a1.z, b, acc[6]); acc[7] = fmaf(a1.w, b, acc[7]);
    }
    __syncthreads();
    if (half == 1) {
        #pragma unroll
        for (int r = 0; r < 8; r++) As[c * 8 + r] = acc[r];
    }
    __syncthreads();
    if (half == 0) {
        #pragma unroll
        for (int r = 0; r < 8; r++)
            Y[(size_t)(r0 + r) * 128 + c] = acc[r] + As[c * 8 + r];
    }
}

// ---------------- merged gates -----------------------------------------------
// grid 96, block 128. enh = g*x + (1-g)*agg, g = sigmoid([x,agg]@W^T + b)
__global__ void __launch_bounds__(128) k_gate2(const float* __restrict__ lig,
                                               const float* __restrict__ poc,
                                               const float* __restrict__ aggl,
                                               const float* __restrict__ aggp,
                                               const float* __restrict__ Wgl,
                                               const float* __restrict__ bgl,
                                               const float* __restrict__ Wgp,
                                               const float* __restrict__ bgp,
                                               float* __restrict__ lige,
                                               float* __restrict__ poce) {
    __shared__ __align__(16) float xs[16 * 128];
    __shared__ __align__(16) float as_[16 * 128];
    int tid = threadIdx.x, bx = blockIdx.x;
    const float* X; const float* A; const float* W; const float* B; float* Y; int r0;
    if (bx < 32) { X = lig; A = aggl; W = Wgl; B = bgl; Y = lige; r0 = bx * 16; }
    else         { X = poc; A = aggp; W = Wgp; B = bgp; Y = poce; r0 = (bx - 32) * 16; }
    for (int idx = tid; idx < 512; idx += 128) {
        ((float4*)xs)[idx] = ((const float4*)(X + (size_t)r0 * 128))[idx];
        ((float4*)as_)[idx] = ((const float4*)(A + (size_t)r0 * 128))[idx];
    }
    __syncthreads();
    float acc[16];
    float bv = B[tid];
    #pragma unroll
    for (int r = 0; r < 16; r++) acc[r] = bv;
    const float* w = W + (size_t)tid * 256;
    #pragma unroll 4
    for (int k = 0; k < 128; k++) {
        float wv = w[k];
        #pragma unroll
        for (int r = 0; r < 16; r++) acc[r] = fmaf(xs[r * 128 + k], wv, acc[r]);
    }
    #pragma unroll 4
    for (int k = 0; k < 128; k++) {
        float wv = w[128 + k];
        #pragma unroll
        for (int r = 0; r < 16; r++) acc[r] = fmaf(as_[r * 128 + k], wv, acc[r]);
    }
    #pragma unroll
    for (int r = 0; r < 16; r++) {
        float g = 1.f / (1.f + __expf(-acc[r]));
        float xv = xs[r * 128 + tid], av = as_[r * 128 + tid];
        Y[(size_t)(r0 + r) * 128 + tid] = g * xv + (1.f - g) * av;
    }
}

// ---------------- merged qkv projections --------------------------------------
// grid(96, 3), block 128. Y[*,384] = X[*,128] @ Wqkv^T + bqkv.
__global__ void __launch_bounds__(128) k_qkv(const float* __restrict__ lige,
                                             const float* __restrict__ poce,
                                             const float* __restrict__ W,
                                             const float* __restrict__ B,
                                             float* __restrict__ qkvl,
                                             float* __restrict__ qkvp) {
    __shared__ __align__(16) float Xs[16 * 128];
    int tid = threadIdx.x, bx = blockIdx.x;
    const float* X; float* Y; int r0;
    if (bx < 32) { X = lige; Y = qkvl; r0 = bx * 16; }
    else         { X = poce; Y = qkvp; r0 = (bx - 32) * 16; }
    int c = blockIdx.y * 128 + tid;
    for (int idx = tid; idx < 512; idx += 128)
        ((float4*)Xs)[idx] = ((const float4*)(X + (size_t)r0 * 128))[idx];
    __syncthreads();
    float acc[16];
    float bv = B[c];
    #pragma unroll
    for (int r = 0; r < 16; r++) acc[r] = bv;
    const float* w = W + (size_t)c * 128;
    #pragma unroll 4
    for (int k = 0; k < 128; k++) {
        float wv = w[k];
        #pragma unroll
        for (int r = 0; r < 16; r++) acc[r] = fmaf(Xs[r * 128 + k], wv, acc[r]);
    }
    #pragma unroll
    for (int r = 0; r < 16; r++) Y[(size_t)(r0 + r) * 384 + c] = acc[r];
}

// ---------------- merged flash attention (both directions) --------------------
// grid(96, 8), block 512: warp-per-query, online softmax, hd=16.
__global__ void __launch_bounds__(512) k_flash2(const float* __restrict__ qkvl,
                                                const float* __restrict__ qkvp,
                                                float* __restrict__ attl,
                                                float* __restrict__ attp) {
    __shared__ __align__(16) float4 Ks[128 * 5];
    __shared__ __align__(16) float4 Vs[128 * 5];
    int bx = blockIdx.x, h = blockIdx.y;
    int tid = threadIdx.x;
    int w = tid >> 5, lane = tid & 31;
    const float* Qb; const float* KVb; float* outp; int nk, i;
    if (bx < 32) { Qb = qkvl; KVb = qkvp; outp = attl; nk = 1024; i = bx * 16 + w; }
    else         { Qb = qkvp; KVb = qkvl; outp = attp; nk = 512; i = (bx - 32) * 16 + w; }

    const float* qp = Qb + (size_t)i * 384 + h * 16;
    float4 q0 = ((const float4*)qp)[0];
    float4 q1 = ((const float4*)qp)[1];
    float4 q2 = ((const float4*)qp)[2];
    float4 q3 = ((const float4*)qp)[3];

    float m = -3.4e38f, l = 0.f;
    float acc[16];
    #pragma unroll
    for (int d = 0; d < 16; d++) acc[d] = 0.f;

    int jload = tid >> 2, cload = tid & 3;
    const float* kbase = KVb + (size_t)jload * 384 + 128 + h * 16 + cload * 4;

    for (int jb = 0; jb < nk; jb += 128) {
        __syncthreads();
        Ks[jload * 5 + cload] = *(const float4*)(kbase + (size_t)jb * 384);
        Vs[jload * 5 + cload] = *(const float4*)(kbase + (size_t)jb * 384 + 128);
        __syncthreads();

        float s[4];
        #pragma unroll
        for (int jj = 0; jj < 4; jj++) {
            const float4* kr = Ks + (jj * 32 + lane) * 5;
            float4 k0 = kr[0], k1 = kr[1], k2 = kr[2], k3 = kr[3];
            float t = q0.x * k0.x;
            t = fmaf(q0.y, k0.y, t); t = fmaf(q0.z, k0.z, t); t = fmaf(q0.w, k0.w, t);
            t = fmaf(q1.x, k1.x, t); t = fmaf(q1.y, k1.y, t);
            t = fmaf(q1.z, k1.z, t); t = fmaf(q1.w, k1.w, t);
            t = fmaf(q2.x, k2.x, t); t = fmaf(q2.y, k2.y, t);
            t = fmaf(q2.z, k2.z, t); t = fmaf(q2.w, k2.w, t);
            t = fmaf(q3.x, k3.x, t); t = fmaf(q3.y, k3.y, t);
            t = fmaf(q3.z, k3.z, t); t = fmaf(q3.w, k3.w, t);
            s[jj] = t * 0.25f;
        }
        float tmax = fmaxf(fmaxf(s[0], s[1]), fmaxf(s[2], s[3]));
        #pragma unroll
        for (int o = 16; o > 0; o >>= 1)
            tmax = fmaxf(tmax, __shfl_xor_sync(0xffffffffu, tmax, o));
        float mnew = fmaxf(m, tmax);
        float corr = __expf(m - mnew);
        m = mnew;
        l *= corr;
        #pragma unroll
        for (int d = 0; d < 16; d++) acc[d] *= corr;
        #pragma unroll
        for (int jj = 0; jj < 4; jj++) {
            float p = __expf(s[jj] - m);
            l += p;
            const float4* vr = Vs + (jj * 32 + lane) * 5;
            float4 v0 = vr[0], v1 = vr[1], v2 = vr[2], v3 = vr[3];
            acc[0]  = fmaf(p, v0.x, acc[0]);  acc[1]  = fmaf(p, v0.y, acc[1]);
            acc[2]  = fmaf(p, v0.z, acc[2]);  acc[3]  = fmaf(p, v0.w, acc[3]);
            acc[4]  = fmaf(p, v1.x, acc[4]);  acc[5]  = fmaf(p, v1.y, acc[5]);
            acc[6]  = fmaf(p, v1.z, acc[6]);  acc[7]  = fmaf(p, v1.w, acc[7]);
            acc[8]  = fmaf(p, v2.x, acc[8]);  acc[9]  = fmaf(p, v2.y, acc[9]);
            acc[10] = fmaf(p, v2.z, acc[10]); acc[11] = fmaf(p, v2.w, acc[11]);
            acc[12] = fmaf(p, v3.x, acc[12]); acc[13] = fmaf(p, v3.y, acc[13]);
            acc[14] = fmaf(p, v3.z, acc[14]); acc[15] = fmaf(p, v3.w, acc[15]);
        }
    }

    #pragma unroll
    for (int o = 16; o > 0; o >>= 1) l += __shfl_xor_sync(0xffffffffu, l, o);
    #pragma unroll
    for (int d = 0; d < 16; d++) {
        #pragma unroll
        for (int o = 16; o > 0; o >>= 1)
            acc[d] += __shfl_xor_sync(0xffffffffu, acc[d], o);
    }
    float val = 0.f;
    #pragma unroll
    for (int d = 0; d < 16; d++) if (lane == d) val = acc[d];
    if (lane < 16) outp[(size_t)i * 128 + h * 16 + lane] = val * (1.f / l);
}

// ---------------- merged out-proj + residual + LN ------------------------------
// grid 96, block 128.
__global__ void __launch_bounds__(128) k_outln2(const float* __restrict__ attl,
                                                const float* __restrict__ attp,
                                                const float* __restrict__ W,
                                                const float* __restrict__ bias,
                                                const float* __restrict__ lige,
                                                const float* __restrict__ poce,
                                                const float* __restrict__ g_l,
                                                const float* __restrict__ be_l,
                                                const float* __restrict__ g_p,
                                                const float* __restrict__ be_p,
                                                float* __restrict__ out) {
    __shared__ __align__(16) float Xs[16 * 128];
    __shared__ __align__(16) float T[16 * 128];
    __shared__ float mu[16], iv[16];
    int tid = threadIdx.x, bx = blockIdx.x;
    const float* X; const float* R; const float* gg; const float* bb; float* O; int r0;
    if (bx < 32) { X = attl; R = lige; gg = g_l; bb = be_l; O = out; r0 = bx * 16; }
    else { X = attp; R = poce; gg = g_p; bb = be_p; O = out + 512 * 128; r0 = (bx - 32) * 16; }
    for (int idx = tid; idx < 512; idx += 128)
        ((float4*)Xs)[idx] = ((const float4*)(X + (size_t)r0 * 128))[idx];
    __syncthreads();
    float acc[16];
    float bv = bias[tid];
    #pragma unroll
    for (int r = 0; r < 16; r++) acc[r] = bv;
    const float* w = W + (size_t)tid * 128;
    #pragma unroll 4
    for (int k = 0; k < 128; k++) {
        float wv = w[k];
        #pragma unroll
        for (int r = 0; r < 16; r++) acc[r] = fmaf(Xs[r * 128 + k], wv, acc[r]);
    }
    #pragma unroll
    for (int r = 0; r < 16; r++)
        T[r * 128 + tid] = acc[r] + R[(size_t)(r0 + r) * 128 + tid];
    __syncthreads();

    int wrp = tid >> 5, lane = tid & 31;
    #pragma unroll
    for (int rr = 0; rr < 4; rr++) {
        int r = wrp * 4 + rr;
        float t0 = T[r * 128 + lane], t1 = T[r * 128 + lane + 32];
        float t2 = T[r * 128 + lane + 64], t3 = T[r * 128 + lane + 96];
        float s = (t0 + t1) + (t2 + t3);
        #pragma unroll
        for (int o = 16; o > 0; o >>= 1) s += __shfl_xor_sync(0xffffffffu, s, o);
        float mean = s * (1.f / 128.f);
        float d0 = t0 - mean, d1 = t1 - mean, d2 = t2 - mean, d3 = t3 - mean;
        float v = (d0 * d0 + d1 * d1) + (d2 * d2 + d3 * d3);
        #pragma unroll
        for (int o = 16; o > 0; o >>= 1) v += __shfl_xor_sync(0xffffffffu, v, o);
        if (lane == 0) {
            mu[r] = mean;
            iv[r] = rsqrtf(v * (1.f / 128.f) + 1e-5f);
        }
    }
    __syncthreads();
    float gc = gg[tid], bc = bb[tid];
    #pragma unroll
    for (int r = 0; r < 16; r++) {
        float t = T[r * 128 + tid];
        O[(size_t)(r0 + r) * 128 + tid] = (t - mu[r]) * iv[r] * gc + bc;
    }
}

// ---------------- launch ------------------------------------------------------
extern "C" void kernel_launch(void* const* d_in, const int* in_sizes, int n_in,
                              void* d_out, int out_size) {
    const float* lf   = (const float*)d_in[0];
    const float* pf   = (const float*)d_in[1];
    const float* lc   = (const float*)d_in[2];
    const float* pc   = (const float*)d_in[3];
    const float* Wl   = (const float*)d_in[4];
    const float* bl   = (const float*)d_in[5];
    const float* Wp   = (const float*)d_in[6];
    const float* bp   = (const float*)d_in[7];
    const float* Wd1  = (const float*)d_in[8];
    const float* bd1  = (const float*)d_in[9];
    const float* Wd2  = (const float*)d_in[10];
    const float* bd2  = (const float*)d_in[11];
    const float* Wd3  = (const float*)d_in[12];
    const float* bd3  = (const float*)d_in[13];
    const float* Wgl  = (const float*)d_in[14];
    const float* bgl  = (const float*)d_in[15];
    const float* Wgp  = (const float*)d_in[16];
    const float* bgp  = (const float*)d_in[17];
    const float* Wqkv = (const float*)d_in[18];
    const float* bqkv = (const float*)d_in[19];
    const float* Wo   = (const float*)d_in[20];
    const float* bo   = (const float*)d_in[21];
    const float* g_l  = (const float*)d_in[22];
    const float* be_l = (const float*)d_in[23];
    const float* g_p  = (const float*)d_in[24];
    const float* be_p = (const float*)d_in[25];
    float* out = (float*)d_out;

    float* SB = nullptr;
    cudaGetSymbolAddress((void**)&SB, g_scratch);
    float* s_lig  = SB + OFF_LIG;
    float* s_poc  = SB + OFF_POC;
    float* s_m    = SB + OFF_M;
    float* s_swl  = SB + OFF_SWL;
    float* s_swp  = SB + OFF_SWP;
    float* s_aggl = SB + OFF_AGGL;
    float* s_aggp = SB + OFF_AGGP;
    float* s_lige = SB + OFF_LIGE;
    float* s_poce = SB + OFF_POCE;
    float* s_qkvl = SB + OFF_QKVL;
    float* s_qkvp = SB + OFF_QKVP;
    float* s_attl = SB + OFF_ATTL;
    float* s_attp = SB + OFF_ATTP;
    float* s_tab  = SB + OFF_TAB;

    k_table<<<32, 128>>>(Wd1, bd1, Wd2, bd2, Wd3, bd3, s_tab);
    k_inproj<<<96, 128>>>(lf, pf, Wl, bl, Wp, bp, s_lig, s_poc);
    k_pairsoft<<<128, 256>>>(lc, pc, s_tab, s_m, s_swl);
    k_transsoft<<<64, 256>>>(s_m, s_swp);
    k_agg<<<192, 256>>>(s_swl, s_swp, s_poc, s_lig, s_aggl, s_aggp);
    k_gate2<<<96, 128>>>(s_lig, s_poc, s_aggl, s_aggp, Wgl, bgl, Wgp, bgp,
                         s_lige, s_poce);
    k_qkv<<<dim3(96, 3), 128>>>(s_lige, s_poce, Wqkv, bqkv, s_qkvl, s_qkvp);
    k_flash2<<<dim3(96, 8), 512>>>(s_qkvl, s_qkvp, s_attl, s_attp);
    k_outln2<<<96, 128>>>(s_attl, s_attp, Wo, bo, s_lige, s_poce,
                          g_l, be_l, g_p, be_p, out);
}